// round 15
// baseline (speedup 1.0000x reference)
#include <cuda_runtime.h>
#include <math.h>
#include <stdint.h>

#define S_LEN 2048
#define DM    2048
#define QH    32
#define KVH   8
#define DH    64
#define KV_W  (2 * KVH * DH)   // 1024

// ---------------- scratch (allocation-free: __device__ globals) ----------------
__device__ float  g_Q[S_LEN * DM];        // fp32 Q proj (rope'd in place)
__device__ float  g_KV[S_LEN * KV_W];     // fp32 KV proj (K rope'd in place)
__device__ float  g_attn[S_LEN * DM];     // fp32 attention output
__device__ float  g_freq[32];
// int8 hi/lo planes + per-row scales
__device__ int8_t g_xh[S_LEN * DM],   g_xl[S_LEN * DM];
__device__ int8_t g_wqh[DM * DM],     g_wql[DM * DM];
__device__ int8_t g_wkvh[KV_W * DM],  g_wkvl[KV_W * DM];
__device__ int8_t g_woh[DM * DM],     g_wol[DM * DM];
__device__ int8_t g_ah[S_LEN * DM],   g_al[S_LEN * DM];
__device__ float  g_xinv[S_LEN], g_wqinv[DM], g_wkvinv[KV_W], g_woinv[DM], g_ainv[S_LEN];

// ============================ helpers ====================================
__device__ __forceinline__ uint32_t smem_u32(const void* p) {
    uint32_t a;
    asm("{ .reg .u64 t; cvta.to.shared.u64 t, %1; cvt.u32.u64 %0, t; }" : "=r"(a) : "l"(p));
    return a;
}
#define CP_ASYNC16(dst, src) \
    asm volatile("cp.async.cg.shared.global [%0], [%1], 16;" :: "r"(dst), "l"(src))
#define CP_COMMIT() asm volatile("cp.async.commit_group;" ::: "memory")
#define CP_WAIT1()  asm volatile("cp.async.wait_group 1;" ::: "memory")
#define CP_WAIT0()  asm volatile("cp.async.wait_group 0;" ::: "memory")

__device__ __forceinline__ uint32_t pack_bf16(float f1_hi, float f0_lo) {
    uint32_t d;
    asm("cvt.rn.bf16x2.f32 %0, %1, %2;" : "=r"(d) : "f"(f1_hi), "f"(f0_lo));
    return d;
}
__device__ __forceinline__ void split2(float f0, float f1, uint32_t& h, uint32_t& l) {
    h = pack_bf16(f1, f0);
    float h0 = __uint_as_float(h << 16);
    float h1 = __uint_as_float(h & 0xFFFF0000u);
    l = pack_bf16(f1 - h1, f0 - h0);
}
__device__ __forceinline__ void mma_bf16(float* d,
                                         uint32_t a0, uint32_t a1, uint32_t a2, uint32_t a3,
                                         uint32_t b0, uint32_t b1) {
    asm volatile(
        "mma.sync.aligned.m16n8k16.row.col.f32.bf16.bf16.f32 "
        "{%0,%1,%2,%3}, {%4,%5,%6,%7}, {%8,%9}, {%0,%1,%2,%3};"
        : "+f"(d[0]), "+f"(d[1]), "+f"(d[2]), "+f"(d[3])
        : "r"(a0), "r"(a1), "r"(a2), "r"(a3), "r"(b0), "r"(b1));
}
__device__ __forceinline__ void mma_s8(int* d,
                                       uint32_t a0, uint32_t a1, uint32_t a2, uint32_t a3,
                                       uint32_t b0, uint32_t b1) {
    asm volatile(
        "mma.sync.aligned.m16n8k32.row.col.s32.s8.s8.s32 "
        "{%0,%1,%2,%3}, {%4,%5,%6,%7}, {%8,%9}, {%0,%1,%2,%3};"
        : "+r"(d[0]), "+r"(d[1]), "+r"(d[2]), "+r"(d[3])
        : "r"(a0), "r"(a1), "r"(a2), "r"(a3), "r"(b0), "r"(b1));
}

// ==============================================================================
// Row quantizer: a_q = round(a * 32639/rowmax) = 256*hi + lo  (hi,lo in s8)
// ==============================================================================
__global__ void quant_rows(const float* __restrict__ in, int8_t* __restrict__ hi,
                           int8_t* __restrict__ lo, float* __restrict__ inv, int K)
{
    const int row = blockIdx.x;
    const int tid = threadIdx.x;
    const float* src = in + (size_t)row * K;
    __shared__ float red[8];

    float mx = 0.0f;
    for (int j = tid * 4; j < K; j += 1024) {
        float4 v = *(const float4*)(src + j);
        mx = fmaxf(mx, fmaxf(fmaxf(fabsf(v.x), fabsf(v.y)), fmaxf(fabsf(v.z), fabsf(v.w))));
    }
#pragma unroll
    for (int off = 16; off > 0; off >>= 1)
        mx = fmaxf(mx, __shfl_xor_sync(0xffffffffu, mx, off));
    if ((tid & 31) == 0) red[tid >> 5] = mx;
    __syncthreads();
    float fm = red[0];
#pragma unroll
    for (int i = 1; i < 8; i++) fm = fmaxf(fm, red[i]);
    fm = fmaxf(fm, 1e-30f);
    const float S = 32639.0f / fm;
    if (tid == 0) inv[row] = fm / 32639.0f;

    for (int j = tid * 4; j < K; j += 1024) {
        float4 v = *(const float4*)(src + j);
        int q0 = __float2int_rn(v.x * S);
        int q1 = __float2int_rn(v.y * S);
        int q2 = __float2int_rn(v.z * S);
        int q3 = __float2int_rn(v.w * S);
        int h0 = (q0 + 128) >> 8, h1 = (q1 + 128) >> 8;
        int h2 = (q2 + 128) >> 8, h3 = (q3 + 128) >> 8;
        *(char4*)(hi + (size_t)row * K + j) =
            make_char4((signed char)h0, (signed char)h1, (signed char)h2, (signed char)h3);
        *(char4*)(lo + (size_t)row * K + j) =
            make_char4((signed char)(q0 - (h0 << 8)), (signed char)(q1 - (h1 << 8)),
                       (signed char)(q2 - (h2 << 8)), (signed char)(q3 - (h3 << 8)));
    }
}

// ==============================================================================
// int8 compensated GEMM: C[M,N] = dequant(Aq @ Bq^T) + bias
// CTA tile 128x64, BK=32, 128 threads (4 warps, 64x32 warp tiles).
// 3 IMMAs (hh -> acc1; hl + lh -> acc2) per (mt,nt) per k32.
// smem: 2 stages of Ah|Al (128x32 s8) + Bh|Bl (64x32 s8), row stride 48B.
// ==============================================================================
#define IST   12                       // uint32 per row (8 data + 4 pad)
#define IA_T  (128 * IST * 4)          // 6144 B
#define IB_T  (64 * IST * 4)           // 3072 B
#define ISTG  (2 * IA_T + 2 * IB_T)    // 18432 B
#define IG_SMEM (2 * ISTG)             // 36864 B

__global__ __launch_bounds__(128, 2)
void igemm(const int8_t* __restrict__ Ah_g, const int8_t* __restrict__ Al_g,
           const int8_t* __restrict__ Bh_g, const int8_t* __restrict__ Bl_g,
           const float* __restrict__ inva, const float* __restrict__ invb,
           const float* __restrict__ bias, float* __restrict__ C,
           int M, int N, int K)
{
    extern __shared__ char smc[];
    const uint32_t smb = smem_u32(smc);

    const int tid  = threadIdx.x;
    const int wid  = tid >> 5;
    const int lane = tid & 31;
    const int qr   = lane >> 2;
    const int qc   = lane & 3;
    const int wm   = (wid & 1) * 64;
    const int wn   = (wid >> 1) * 32;
    const int brow = blockIdx.y * 128;
    const int bcol = blockIdx.x * 64;

    // loader: 6 x 16B chunks per thread per stage (768 total)
    const int8_t* gsrc[6];
    uint32_t gdst[6];
#pragma unroll
    for (int j = 0; j < 6; j++) {
        int i = tid + j * 128;
        const int8_t* g;
        uint32_t toff;
        if (i < 512) {
            int r = (i & 255) >> 1, hf = i & 1;
            g = (i < 256 ? Ah_g : Al_g) + (size_t)(brow + r) * K + hf * 16;
            toff = (i < 256 ? 0u : (uint32_t)IA_T) + (uint32_t)(r * 48 + hf * 16);
        } else {
            int i2 = i - 512;
            int r = (i2 & 127) >> 1, hf = i2 & 1;
            g = (i2 < 128 ? Bh_g : Bl_g) + (size_t)(bcol + r) * K + hf * 16;
            toff = 2u * IA_T + (i2 < 128 ? 0u : (uint32_t)IB_T) + (uint32_t)(r * 48 + hf * 16);
        }
        gsrc[j] = g;
        gdst[j] = smb + toff;
    }

    const int NT = K >> 5;
    auto issue = [&](int kt) {
        const uint32_t so = (uint32_t)(kt & 1) * ISTG;
#pragma unroll
        for (int j = 0; j < 6; j++) CP_ASYNC16(gdst[j] + so, gsrc[j] + kt * 32);
    };

    int acc1[4][4][4], acc2[4][4][4];
#pragma unroll
    for (int mt = 0; mt < 4; mt++)
#pragma unroll
        for (int nt = 0; nt < 4; nt++)
#pragma unroll
            for (int i = 0; i < 4; i++) { acc1[mt][nt][i] = 0; acc2[mt][nt][i] = 0; }

    issue(0); CP_COMMIT();

    for (int kt = 0; kt < NT; kt++) {
        if (kt + 1 < NT) { issue(kt + 1); CP_COMMIT(); CP_WAIT1(); }
        else             { CP_WAIT0(); }
        __syncthreads();

        const uint32_t* Ah = (const uint32_t*)(smc + (kt & 1) * ISTG);
        const uint32_t* Al = Ah + IA_T / 4;
        const uint32_t* Bh = Ah + 2 * (IA_T / 4);
        const uint32_t* Bl = Bh + IB_T / 4;

        uint32_t bh[4][2], bl[4][2];
#pragma unroll
        for (int nt = 0; nt < 4; nt++) {
            const int o = (wn + nt * 8 + qr) * IST + qc;
            bh[nt][0] = Bh[o]; bh[nt][1] = Bh[o + 4];
            bl[nt][0] = Bl[o]; bl[nt][1] = Bl[o + 4];
        }
#pragma unroll
        for (int mt = 0; mt < 4; mt++) {
            const int o = (wm + mt * 16 + qr) * IST + qc;
            uint32_t ah0 = Ah[o], ah1 = Ah[o + 8 * IST];
            uint32_t ah2 = Ah[o + 4], ah3 = Ah[o + 8 * IST + 4];
            uint32_t al0 = Al[o], al1 = Al[o + 8 * IST];
            uint32_t al2 = Al[o + 4], al3 = Al[o + 8 * IST + 4];
#pragma unroll
            for (int nt = 0; nt < 4; nt++) {
                mma_s8(acc1[mt][nt], ah0, ah1, ah2, ah3, bh[nt][0], bh[nt][1]);
                mma_s8(acc2[mt][nt], ah0, ah1, ah2, ah3, bl[nt][0], bl[nt][1]);
                mma_s8(acc2[mt][nt], al0, al1, al2, al3, bh[nt][0], bh[nt][1]);
            }
        }
        __syncthreads();
    }

    // epilogue: dequant + bias
#pragma unroll
    for (int mt = 0; mt < 4; mt++) {
        const int r0 = brow + wm + mt * 16 + qr;
        const float ia0 = inva[r0], ia1 = inva[r0 + 8];
#pragma unroll
        for (int nt = 0; nt < 4; nt++) {
            const int col = bcol + wn + nt * 8 + 2 * qc;
            const float ib0 = invb[col], ib1 = invb[col + 1];
            const float b0 = bias[col], b1 = bias[col + 1];
            float v0 = (65536.0f * (float)acc1[mt][nt][0] + 256.0f * (float)acc2[mt][nt][0]);
            float v1 = (65536.0f * (float)acc1[mt][nt][1] + 256.0f * (float)acc2[mt][nt][1]);
            float v2 = (65536.0f * (float)acc1[mt][nt][2] + 256.0f * (float)acc2[mt][nt][2]);
            float v3 = (65536.0f * (float)acc1[mt][nt][3] + 256.0f * (float)acc2[mt][nt][3]);
            *(float2*)(C + (size_t)r0 * N + col) =
                make_float2(v0 * ia0 * ib0 + b0, v1 * ia0 * ib1 + b1);
            *(float2*)(C + (size_t)(r0 + 8) * N + col) =
                make_float2(v2 * ia1 * ib0 + b0, v3 * ia1 * ib1 + b1);
        }
    }
}

// ==============================================================================
// RoPE (R13 exact)
// ==============================================================================
__global__ void freq_kernel()
{
    int j = threadIdx.x;
    if (j < 32) g_freq[j] = (float)pow(10000.0, -(double)j / 32.0);
}

__global__ void rope_kernel(float* __restrict__ X, int H, int rowstride)
{
    int idx = blockIdx.x * blockDim.x + threadIdx.x;
    int total = S_LEN * H * (DH / 2);
    if (idx >= total) return;

    int j = idx & 31;
    int t = idx >> 5;
    int h = t % H;
    int s = t / H;

    float theta = (float)s * g_freq[j];
    float sn, cs;
    sincosf(theta, &sn, &cs);

    float* p = X + (size_t)s * rowstride + h * DH + 2 * j;
    float2 v = *(float2*)p;
    float2 o;
    o.x = v.x * cs - v.y * sn;
    o.y = v.x * sn + v.y * cs;
    *(float2*)p = o;
}

// ==============================================================================
// Flash attention (R13 EXACT — proven 1049us component)
// ==============================================================================
#define QST 36
#define KST 36
#define VST 68
#define VBUF_F (64 * VST)
#define OFF_KHL 36864
#define OFF_VS  (OFF_KHL + 64 * KST * 8)
#define FA_SMEM (OFF_VS + 2 * VBUF_F * 4)     // 90112

__global__ __launch_bounds__(128, 2)
void flash_attn_bf16(const float* __restrict__ Q, const float* __restrict__ KV,
                     float* __restrict__ O)
{
    extern __shared__ char smc[];
    const uint32_t smb = smem_u32(smc);
    uint2* QHL = (uint2*)smc;
    uint2* KHL = (uint2*)(smc + OFF_KHL);
    float* Vs  = (float*)(smc + OFF_VS);

    const int qt   = blockIdx.x;
    const int h    = blockIdx.y;
    const int hk   = h >> 2;
    const int tid  = threadIdx.x;
    const int wid  = tid >> 5;
    const int lane = tid & 31;
    const int qr   = lane >> 2;
    const int qc   = lane & 3;
    const int wm   = wid * 32;

    const int lrow  = tid >> 1;
    const int lhalf = (tid & 1) * 32;
    const float* kbase = KV + (size_t)lrow * KV_W + hk * DH + lhalf;
    const float* vbase = kbase + KVH * DH;
    uint2* kdst = KHL + lrow * KST + (lhalf >> 1);
    const uint32_t vdst_off = smb + OFF_VS + (uint32_t)(lrow * VST + lhalf) * 4;

    auto issue_V = [&](int kt) {
        const float* src = vbase + (size_t)(kt * 64) * KV_W;
        uint32_t dst = vdst_off + (uint32_t)((kt & 1) * VBUF_F) * 4;
#pragma unroll
        for (int j = 0; j < 8; j++) CP_ASYNC16(dst + 16 * j, src + 4 * j);
    };

    {
        const float* src = Q + (size_t)(qt * 128 + tid) * DM + h * DH;
        uint2* dst = QHL + tid * QST;
#pragma unroll
        for (int j = 0; j < 16; j++) {
            float4 v = *(const float4*)(src + 4 * j);
            uint32_t h01, l01, h23, l23;
            split2(v.x * 0.125f, v.y * 0.125f, h01, l01);
            split2(v.z * 0.125f, v.w * 0.125f, h23, l23);
            *(uint4*)(dst + 2 * j) = make_uint4(h01, l01, h23, l23);
        }
    }

    issue_V(0); CP_COMMIT();
    float4 kreg[8];
    {
        const float* src = kbase;
#pragma unroll
        for (int j = 0; j < 8; j++) kreg[j] = *(const float4*)(src + 4 * j);
    }

    float m_i[2][2], l_i[2][2];
#pragma unroll
    for (int mt = 0; mt < 2; mt++)
#pragma unroll
        for (int hf = 0; hf < 2; hf++) { m_i[mt][hf] = -1e30f; l_i[mt][hf] = 0.0f; }

    float acc[2][8][4];
#pragma unroll
    for (int mt = 0; mt < 2; mt++)
#pragma unroll
        for (int nt = 0; nt < 8; nt++)
#pragma unroll
            for (int i = 0; i < 4; i++) acc[mt][nt][i] = 0.0f;

    for (int kt = 0; kt < 32; kt++) {
        __syncthreads();

#pragma unroll
        for (int j = 0; j < 8; j++) {
            uint32_t h01, l01, h23, l23;
            split2(kreg[j].x, kreg[j].y, h01, l01);
            split2(kreg[j].z, kreg[j].w, h23, l23);
            *(uint4*)(kdst + 2 * j) = make_uint4(h01, l01, h23, l23);
        }
        if (kt + 1 < 32) {
            const float* src = kbase + (size_t)((kt + 1) * 64) * KV_W;
#pragma unroll
            for (int j = 0; j < 8; j++) kreg[j] = *(const float4*)(src + 4 * j);
        }
        if (kt + 1 < 32) { issue_V(kt + 1); CP_COMMIT(); CP_WAIT1(); }
        else             { CP_WAIT0(); }
        __syncthreads();

        const float* Vcur = Vs + (kt & 1) * VBUF_F;

        float s[2][8][4];
#pragma unroll
        for (int mt = 0; mt < 2; mt++)
#pragma unroll
            for (int nt = 0; nt < 8; nt++)
#pragma unroll
                for (int i = 0; i < 4; i++) s[mt][nt][i] = 0.0f;

#pragma unroll
        for (int ks = 0; ks < 4; ks++) {
            uint2 bk[8][2];
#pragma unroll
            for (int nt = 0; nt < 8; nt++) {
                const int kb = (nt * 8 + qr) * KST + ks * 8 + qc;
                bk[nt][0] = KHL[kb];
                bk[nt][1] = KHL[kb + 4];
            }
#pragma unroll
            for (int mt = 0; mt < 2; mt++) {
                const int qb = (wm + mt * 16 + qr) * QST + ks * 8 + qc;
                uint2 a0 = QHL[qb];
                uint2 a1 = QHL[qb + 8 * QST];
                uint2 a2 = QHL[qb + 4];
                uint2 a3 = QHL[qb + 8 * QST + 4];
#pragma unroll
                for (int nt = 0; nt < 8; nt++) {
                    mma_bf16(s[mt][nt], a0.x, a1.x, a2.x, a3.x, bk[nt][0].x, bk[nt][1].x);
                    mma_bf16(s[mt][nt], a0.x, a1.x, a2.x, a3.x, bk[nt][0].y, bk[nt][1].y);
                    mma_bf16(s[mt][nt], a0.y, a1.y, a2.y, a3.y, bk[nt][0].x, bk[nt][1].x);
                }
            }
        }

#pragma unroll
        for (int mt = 0; mt < 2; mt++) {
#pragma unroll
            for (int hf = 0; hf < 2; hf++) {
                float mx = -1e30f;
#pragma unroll
                for (int nt = 0; nt < 8; nt++)
                    mx = fmaxf(mx, fmaxf(s[mt][nt][2 * hf], s[mt][nt][2 * hf + 1]));
                mx = fmaxf(mx, __shfl_xor_sync(0xffffffffu, mx, 1));
                mx = fmaxf(mx, __shfl_xor_sync(0xffffffffu, mx, 2));
                float m_new = fmaxf(m_i[mt][hf], mx);
                float alpha = __expf(m_i[mt][hf] - m_new);
                float rs = 0.0f;
#pragma unroll
                for (int nt = 0; nt < 8; nt++) {
                    s[mt][nt][2 * hf]     = __expf(s[mt][nt][2 * hf] - m_new);
                    s[mt][nt][2 * hf + 1] = __expf(s[mt][nt][2 * hf + 1] - m_new);
                    rs += s[mt][nt][2 * hf] + s[mt][nt][2 * hf + 1];
                }
                rs += __shfl_xor_sync(0xffffffffu, rs, 1);
                rs += __shfl_xor_sync(0xffffffffu, rs, 2);
                l_i[mt][hf] = l_i[mt][hf] * alpha + rs;
                m_i[mt][hf] = m_new;
#pragma unroll
                for (int nt = 0; nt < 8; nt++) {
                    acc[mt][nt][2 * hf]     *= alpha;
                    acc[mt][nt][2 * hf + 1] *= alpha;
                }
            }
        }

#pragma unroll
        for (int ks = 0; ks < 4; ks++) {
            uint32_t vh[8][2], vl[8][2];
#pragma unroll
            for (int nt = 0; nt < 8; nt++) {
                const int n  = nt * 8 + qr;
                const int k0 = ks * 16 + 2 * qc;
                float f0 = Vcur[k0 * VST + n];
                float f1 = Vcur[(k0 + 1) * VST + n];
                split2(f0, f1, vh[nt][0], vl[nt][0]);
                float f2 = Vcur[(k0 + 8) * VST + n];
                float f3 = Vcur[(k0 + 9) * VST + n];
                split2(f2, f3, vh[nt][1], vl[nt][1]);
            }
#pragma unroll
            for (int mt = 0; mt < 2; mt++) {
                uint32_t ph0, pl0, ph1, pl1, ph2, pl2, ph3, pl3;
                split2(s[mt][2 * ks][0],     s[mt][2 * ks][1],     ph0, pl0);
                split2(s[mt][2 * ks][2],     s[mt][2 * ks][3],     ph1, pl1);
                split2(s[mt][2 * ks + 1][0], s[mt][2 * ks + 1][1], ph2, pl2);
                split2(s[mt][2 * ks + 1][2], s[mt][2 * ks + 1][3], ph3, pl3);
#pragma unroll
                for (int nt = 0; nt < 8; nt++) {
                    mma_bf16(acc[mt][nt], ph0, ph1, ph2, ph3, vh[nt][0], vh[nt][1]);
                    mma_bf16(acc[mt][nt], ph0, ph1, ph2, ph3, vl[nt][0], vl[nt][1]);
                    mma_bf16(acc[mt][nt], pl0, pl1, pl2, pl3, vh[nt][0], vh[nt][1]);
                }
            }
        }
    }

#pragma unroll
    for (int mt = 0; mt < 2; mt++) {
        const float i0 = 1.0f / l_i[mt][0];
        const float i1 = 1.0f / l_i[mt][1];
        float* d0 = O + (size_t)(qt * 128 + wm + mt * 16 + qr) * DM + h * DH;
        float* d1 = d0 + (size_t)8 * DM;
#pragma unroll
        for (int nt = 0; nt < 8; nt++) {
            *(float2*)(d0 + nt * 8 + 2 * qc) =
                make_float2(acc[mt][nt][0] * i0, acc[mt][nt][1] * i0);
            *(float2*)(d1 + nt * 8 + 2 * qc) =
                make_float2(acc[mt][nt][2] * i1, acc[mt][nt][3] * i1);
        }
    }
}

// ==============================================================================
// launch
// ==============================================================================
extern "C" void kernel_launch(void* const* d_in, const int* in_sizes, int n_in,
                              void* d_out, int out_size)
{
    const float* x     = (const float*)d_in[0];
    const float* W_q   = (const float*)d_in[1];
    const float* b_q   = (const float*)d_in[2];
    const float* W_kv  = (const float*)d_in[3];
    const float* b_kv  = (const float*)d_in[4];
    const float* W_out = (const float*)d_in[5];
    const float* b_out = (const float*)d_in[6];
    float* out = (float*)d_out;

    float *qbuf, *kvbuf, *abuf;
    int8_t *xh, *xl, *wqh, *wql, *wkvh, *wkvl, *woh, *wol, *ah, *al;
    float *xinv, *wqinv, *wkvinv, *woinv, *ainv;
    cudaGetSymbolAddress((void**)&qbuf,  g_Q);
    cudaGetSymbolAddress((void**)&kvbuf, g_KV);
    cudaGetSymbolAddress((void**)&abuf,  g_attn);
    cudaGetSymbolAddress((void**)&xh,    g_xh);
    cudaGetSymbolAddress((void**)&xl,    g_xl);
    cudaGetSymbolAddress((void**)&wqh,   g_wqh);
    cudaGetSymbolAddress((void**)&wql,   g_wql);
    cudaGetSymbolAddress((void**)&wkvh,  g_wkvh);
    cudaGetSymbolAddress((void**)&wkvl,  g_wkvl);
    cudaGetSymbolAddress((void**)&woh,   g_woh);
    cudaGetSymbolAddress((void**)&wol,   g_wol);
    cudaGetSymbolAddress((void**)&ah,    g_ah);
    cudaGetSymbolAddress((void**)&al,    g_al);
    cudaGetSymbolAddress((void**)&xinv,  g_xinv);
    cudaGetSymbolAddress((void**)&wqinv, g_wqinv);
    cudaGetSymbolAddress((void**)&wkvinv, g_wkvinv);
    cudaGetSymbolAddress((void**)&woinv, g_woinv);
    cudaGetSymbolAddress((void**)&ainv,  g_ainv);

    cudaFuncSetAttribute(flash_attn_bf16, cudaFuncAttributeMaxDynamicSharedMemorySize, FA_SMEM);
    cudaFuncSetAttribute(igemm, cudaFuncAttributeMaxDynamicSharedMemorySize, IG_SMEM);

    // quantize inputs + weights
    quant_rows<<<S_LEN, 256>>>(x, xh, xl, xinv, DM);
    quant_rows<<<DM, 256>>>(W_q, wqh, wql, wqinv, DM);
    quant_rows<<<KV_W, 256>>>(W_kv, wkvh, wkvl, wkvinv, DM);
    quant_rows<<<DM, 256>>>(W_out, woh, wol, woinv, DM);

    // projections (int8 compensated)
    igemm<<<dim3(DM / 64, S_LEN / 128), 128, IG_SMEM>>>(
        xh, xl, wqh, wql, xinv, wqinv, b_q, qbuf, S_LEN, DM, DM);
    igemm<<<dim3(KV_W / 64, S_LEN / 128), 128, IG_SMEM>>>(
        xh, xl, wkvh, wkvl, xinv, wkvinv, b_kv, kvbuf, S_LEN, KV_W, DM);

    // RoPE (R13 exact)
    freq_kernel<<<1, 32>>>();
    rope_kernel<<<(S_LEN * QH * 32 + 255) / 256, 256>>>(qbuf, QH, DM);
    rope_kernel<<<(S_LEN * KVH * 32 + 255) / 256, 256>>>(kvbuf, KVH, KV_W);

    // Flash attention (R13 exact)
    flash_attn_bf16<<<dim3(S_LEN / 128, QH), 128, FA_SMEM>>>(qbuf, kvbuf, abuf);

    // quantize attention output, then out-projection
    quant_rows<<<S_LEN, 256>>>(abuf, ah, al, ainv, DM);
    igemm<<<dim3(DM / 64, S_LEN / 128), 128, IG_SMEM>>>(
        ah, al, woh, wol, ainv, woinv, b_out, out, S_LEN, DM, DM);
}

// round 16
// speedup vs baseline: 1.6224x; 1.6224x over previous
#include <cuda_runtime.h>
#include <cuda_fp16.h>
#include <math.h>
#include <stdint.h>

#define S_LEN 2048
#define DM    2048
#define QH    32
#define KVH   8
#define DH    64
#define KV_W  (2 * KVH * DH)   // 1024

// ---------------- scratch (allocation-free: __device__ globals) ----------------
__device__ float g_Q[S_LEN * DM];        // fp32 Q proj (rope'd in place)
__device__ float g_KV[S_LEN * KV_W];     // fp32 KV proj (K rope'd in place)
__device__ float g_attn[S_LEN * DM];     // fp32 attention output
__device__ float g_freq[32];             // rope frequency table

// ============================ helpers ====================================
__device__ __forceinline__ uint32_t smem_u32(const void* p) {
    uint32_t a;
    asm("{ .reg .u64 t; cvta.to.shared.u64 t, %1; cvt.u32.u64 %0, t; }" : "=r"(a) : "l"(p));
    return a;
}
#define CP_ASYNC16(dst, src) \
    asm volatile("cp.async.cg.shared.global [%0], [%1], 16;" :: "r"(dst), "l"(src))
#define CP_COMMIT() asm volatile("cp.async.commit_group;" ::: "memory")
#define CP_WAIT1()  asm volatile("cp.async.wait_group 1;" ::: "memory")
#define CP_WAIT0()  asm volatile("cp.async.wait_group 0;" ::: "memory")

// ---- bf16 3-term helpers (attention, R13 exact) ----
__device__ __forceinline__ uint32_t pack_bf16(float f1_hi, float f0_lo) {
    uint32_t d;
    asm("cvt.rn.bf16x2.f32 %0, %1, %2;" : "=r"(d) : "f"(f1_hi), "f"(f0_lo));
    return d;
}
__device__ __forceinline__ void split2(float f0, float f1, uint32_t& h, uint32_t& l) {
    h = pack_bf16(f1, f0);
    float h0 = __uint_as_float(h << 16);
    float h1 = __uint_as_float(h & 0xFFFF0000u);
    l = pack_bf16(f1 - h1, f0 - f1 + f1 - h1 == 0.0f ? f1 - h1 : f1 - h1); // placeholder (unused)
    l = pack_bf16(f1 - h1, f0 - h0);
}
__device__ __forceinline__ void mma_bf16(float* d,
                                         uint32_t a0, uint32_t a1, uint32_t a2, uint32_t a3,
                                         uint32_t b0, uint32_t b1) {
    asm volatile(
        "mma.sync.aligned.m16n8k16.row.col.f32.bf16.bf16.f32 "
        "{%0,%1,%2,%3}, {%4,%5,%6,%7}, {%8,%9}, {%0,%1,%2,%3};"
        : "+f"(d[0]), "+f"(d[1]), "+f"(d[2]), "+f"(d[3])
        : "r"(a0), "r"(a1), "r"(a2), "r"(a3), "r"(b0), "r"(b1));
}

// ---- fp16 2-term helpers (projection GEMMs) ----
__device__ __forceinline__ uint32_t pack_f16(float f0_lo, float f1_hi) {
    __half2 h = __floats2half2_rn(f0_lo, f1_hi);
    return *(uint32_t*)&h;
}
// A-split: a = ah + al with fp16 rounding (al exact to ~2^-23 of a)
__device__ __forceinline__ void split2h(float f0, float f1, uint32_t& h, uint32_t& l) {
    __half2 hh = __floats2half2_rn(f0, f1);
    float2 hf = __half22float2(hh);
    __half2 ll = __floats2half2_rn(f0 - hf.x, f1 - hf.y);
    h = *(uint32_t*)&hh;
    l = *(uint32_t*)&ll;
}
__device__ __forceinline__ void mma_f16(float* d,
                                        uint32_t a0, uint32_t a1, uint32_t a2, uint32_t a3,
                                        uint32_t b0, uint32_t b1) {
    asm volatile(
        "mma.sync.aligned.m16n8k16.row.col.f32.f16.f16.f32 "
        "{%0,%1,%2,%3}, {%4,%5,%6,%7}, {%8,%9}, {%0,%1,%2,%3};"
        : "+f"(d[0]), "+f"(d[1]), "+f"(d[2]), "+f"(d[3])
        : "r"(a0), "r"(a1), "r"(a2), "r"(a3), "r"(b0), "r"(b1));
}

// ==============================================================================
// 2-term FP16 GEMM via mma.sync + cp.async (R13 pipeline/layout, new numerics):
// C = A @ B^T + bias.  A = Ah + Al (fp16 split, exact); B = Bh (fp16 rn).
// 2 MMAs per (mt,nt) per k16: Ah*Bh + Al*Bh.  Error ~2^-12/sqrt(3) per GEMM.
// 128x128 CTA tile, BK=16, 128 threads (4 warps, 64x64 warp tiles).
// ==============================================================================
#define BK     16
#define SSTR   24
#define ST_F   (128 * SSTR)
#define STG_F  (2 * ST_F)
#define NSTG   3
#define TG_SMEM (NSTG * STG_F * 4)  // 73728 B

__global__ __launch_bounds__(128, 2)
void tgemm_f16_nt_bias(const float* __restrict__ A, const float* __restrict__ B,
                       const float* __restrict__ bias, float* __restrict__ C,
                       int M, int N, int K)
{
    extern __shared__ float sm[];
    const uint32_t smb = smem_u32(sm);

    const int tid  = threadIdx.x;
    const int wid  = tid >> 5;
    const int lane = tid & 31;
    const int qr   = lane >> 2;
    const int qc   = lane & 3;
    const int wm   = (wid & 1) * 64;
    const int wn   = (wid >> 1) * 64;
    const int brow = blockIdx.y * 128;
    const int bcol = blockIdx.x * 128;

    const float* Ag = A + (size_t)(brow + tid) * K;
    const float* Bg = B + (size_t)(bcol + tid) * K;
    const uint32_t dst_off = (uint32_t)(tid * SSTR) * 4;

    const int NT = K / BK;

    auto issue_stage = [&](int kt) {
        const uint32_t da = smb + (uint32_t)((kt % NSTG) * STG_F) * 4 + dst_off;
        const uint32_t db = da + ST_F * 4;
        const float* sa = Ag + kt * BK;
        const float* sb = Bg + kt * BK;
#pragma unroll
        for (int j = 0; j < 4; j++) {
            CP_ASYNC16(da + 16 * j, sa + 4 * j);
            CP_ASYNC16(db + 16 * j, sb + 4 * j);
        }
    };

    float acc[4][8][4];
#pragma unroll
    for (int mt = 0; mt < 4; mt++)
#pragma unroll
        for (int nt = 0; nt < 8; nt++)
#pragma unroll
            for (int i = 0; i < 4; i++) acc[mt][nt][i] = 0.0f;

    issue_stage(0); CP_COMMIT();
    issue_stage(1); CP_COMMIT();

    for (int kt = 0; kt < NT; kt++) {
        CP_WAIT1();
        __syncthreads();

        if (kt + 2 < NT) issue_stage(kt + 2);
        CP_COMMIT();

        const float* As = sm + (kt % NSTG) * STG_F;
        const float* Bs = As + ST_F;

        // B fragments: fp16 hi only (2 cvt per frag pair)
        uint32_t bh[8][2];
#pragma unroll
        for (int nt = 0; nt < 8; nt++) {
            const int off = (wn + nt * 8 + qr) * SSTR + 2 * qc;
            float2 f = *(const float2*)&Bs[off];
            float2 g = *(const float2*)&Bs[off + 8];
            bh[nt][0] = pack_f16(f.x, f.y);
            bh[nt][1] = pack_f16(g.x, g.y);
        }
#pragma unroll
        for (int mt = 0; mt < 4; mt++) {
            const int off = (wm + mt * 16 + qr) * SSTR + 2 * qc;
            float2 f0 = *(const float2*)&As[off];
            float2 f1 = *(const float2*)&As[off + 8 * SSTR];
            float2 f2 = *(const float2*)&As[off + 8];
            float2 f3 = *(const float2*)&As[off + 8 * SSTR + 8];
            uint32_t ah0, ah1, ah2, ah3, al0, al1, al2, al3;
            split2h(f0.x, f0.y, ah0, al0);
            split2h(f1.x, f1.y, ah1, al1);
            split2h(f2.x, f2.y, ah2, al2);
            split2h(f3.x, f3.y, ah3, al3);
#pragma unroll
            for (int nt = 0; nt < 8; nt++) {
                mma_f16(acc[mt][nt], ah0, ah1, ah2, ah3, bh[nt][0], bh[nt][1]);
                mma_f16(acc[mt][nt], al0, al1, al2, al3, bh[nt][0], bh[nt][1]);
            }
        }
        __syncthreads();
    }

#pragma unroll
    for (int mt = 0; mt < 4; mt++) {
        const int row = brow + wm + mt * 16 + qr;
#pragma unroll
        for (int nt = 0; nt < 8; nt++) {
            const int col = bcol + wn + nt * 8 + qc * 2;
            const float b0 = bias[col], b1 = bias[col + 1];
            *(float2*)(C + (size_t)row * N + col) =
                make_float2(acc[mt][nt][0] + b0, acc[mt][nt][1] + b1);
            *(float2*)(C + (size_t)(row + 8) * N + col) =
                make_float2(acc[mt][nt][2] + b0, acc[mt][nt][3] + b1);
        }
    }
}

// ==============================================================================
// RoPE (R13 exact)
// ==============================================================================
__global__ void freq_kernel()
{
    int j = threadIdx.x;
    if (j < 32) g_freq[j] = (float)pow(10000.0, -(double)j / 32.0);
}

__global__ void rope_kernel(float* __restrict__ X, int H, int rowstride)
{
    int idx = blockIdx.x * blockDim.x + threadIdx.x;
    int total = S_LEN * H * (DH / 2);
    if (idx >= total) return;

    int j = idx & 31;
    int t = idx >> 5;
    int h = t % H;
    int s = t / H;

    float theta = (float)s * g_freq[j];
    float sn, cs;
    sincosf(theta, &sn, &cs);

    float* p = X + (size_t)s * rowstride + h * DH + 2 * j;
    float2 v = *(float2*)p;
    float2 o;
    o.x = v.x * cs - v.y * sn;
    o.y = v.x * sn + v.y * cs;
    *(float2*)p = o;
}

// ==============================================================================
// Flash attention (R13 EXACT — proven 1049us component; 3-term bf16)
// ==============================================================================
#define QST 36
#define KST 36
#define VST 68
#define VBUF_F (64 * VST)
#define OFF_KHL 36864
#define OFF_VS  (OFF_KHL + 64 * KST * 8)
#define FA_SMEM (OFF_VS + 2 * VBUF_F * 4)     // 90112

__global__ __launch_bounds__(128, 2)
void flash_attn_bf16(const float* __restrict__ Q, const float* __restrict__ KV,
                     float* __restrict__ O)
{
    extern __shared__ char smc[];
    const uint32_t smb = smem_u32(smc);
    uint2* QHL = (uint2*)smc;
    uint2* KHL = (uint2*)(smc + OFF_KHL);
    float* Vs  = (float*)(smc + OFF_VS);

    const int qt   = blockIdx.x;
    const int h    = blockIdx.y;
    const int hk   = h >> 2;
    const int tid  = threadIdx.x;
    const int wid  = tid >> 5;
    const int lane = tid & 31;
    const int qr   = lane >> 2;
    const int qc   = lane & 3;
    const int wm   = wid * 32;

    const int lrow  = tid >> 1;
    const int lhalf = (tid & 1) * 32;
    const float* kbase = KV + (size_t)lrow * KV_W + hk * DH + lhalf;
    const float* vbase = kbase + KVH * DH;
    uint2* kdst = KHL + lrow * KST + (lhalf >> 1);
    const uint32_t vdst_off = smb + OFF_VS + (uint32_t)(lrow * VST + lhalf) * 4;

    auto issue_V = [&](int kt) {
        const float* src = vbase + (size_t)(kt * 64) * KV_W;
        uint32_t dst = vdst_off + (uint32_t)((kt & 1) * VBUF_F) * 4;
#pragma unroll
        for (int j = 0; j < 8; j++) CP_ASYNC16(dst + 16 * j, src + 4 * j);
    };

    {
        const float* src = Q + (size_t)(qt * 128 + tid) * DM + h * DH;
        uint2* dst = QHL + tid * QST;
#pragma unroll
        for (int j = 0; j < 16; j++) {
            float4 v = *(const float4*)(src + 4 * j);
            uint32_t h01, l01, h23, l23;
            split2(v.x * 0.125f, v.y * 0.125f, h01, l01);
            split2(v.z * 0.125f, v.w * 0.125f, h23, l23);
            *(uint4*)(dst + 2 * j) = make_uint4(h01, l01, h23, l23);
        }
    }

    issue_V(0); CP_COMMIT();
    float4 kreg[8];
    {
        const float* src = kbase;
#pragma unroll
        for (int j = 0; j < 8; j++) kreg[j] = *(const float4*)(src + 4 * j);
    }

    float m_i[2][2], l_i[2][2];
#pragma unroll
    for (int mt = 0; mt < 2; mt++)
#pragma unroll
        for (int hf = 0; hf < 2; hf++) { m_i[mt][hf] = -1e30f; l_i[mt][hf] = 0.0f; }

    float acc[2][8][4];
#pragma unroll
    for (int mt = 0; mt < 2; mt++)
#pragma unroll
        for (int nt = 0; nt < 8; nt++)
#pragma unroll
            for (int i = 0; i < 4; i++) acc[mt][nt][i] = 0.0f;

    for (int kt = 0; kt < 32; kt++) {
        __syncthreads();

#pragma unroll
        for (int j = 0; j < 8; j++) {
            uint32_t h01, l01, h23, l23;
            split2(kreg[j].x, kreg[j].y, h01, l01);
            split2(kreg[j].z, kreg[j].w, h23, l23);
            *(uint4*)(kdst + 2 * j) = make_uint4(h01, l01, h23, l23);
        }
        if (kt + 1 < 32) {
            const float* src = kbase + (size_t)((kt + 1) * 64) * KV_W;
#pragma unroll
            for (int j = 0; j < 8; j++) kreg[j] = *(const float4*)(src + 4 * j);
        }
        if (kt + 1 < 32) { issue_V(kt + 1); CP_COMMIT(); CP_WAIT1(); }
        else             { CP_WAIT0(); }
        __syncthreads();

        const float* Vcur = Vs + (kt & 1) * VBUF_F;

        float s[2][8][4];
#pragma unroll
        for (int mt = 0; mt < 2; mt++)
#pragma unroll
            for (int nt = 0; nt < 8; nt++)
#pragma unroll
                for (int i = 0; i < 4; i++) s[mt][nt][i] = 0.0f;

#pragma unroll
        for (int ks = 0; ks < 4; ks++) {
            uint2 bk[8][2];
#pragma unroll
            for (int nt = 0; nt < 8; nt++) {
                const int kb = (nt * 8 + qr) * KST + ks * 8 + qc;
                bk[nt][0] = KHL[kb];
                bk[nt][1] = KHL[kb + 4];
            }
#pragma unroll
            for (int mt = 0; mt < 2; mt++) {
                const int qb = (wm + mt * 16 + qr) * QST + ks * 8 + qc;
                uint2 a0 = QHL[qb];
                uint2 a1 = QHL[qb + 8 * QST];
                uint2 a2 = QHL[qb + 4];
                uint2 a3 = QHL[qb + 8 * QST + 4];
#pragma unroll
                for (int nt = 0; nt < 8; nt++) {
                    mma_bf16(s[mt][nt], a0.x, a1.x, a2.x, a3.x, bk[nt][0].x, bk[nt][1].x);
                    mma_bf16(s[mt][nt], a0.x, a1.x, a2.x, a3.x, bk[nt][0].y, bk[nt][1].y);
                    mma_bf16(s[mt][nt], a0.y, a1.y, a2.y, a3.y, bk[nt][0].x, bk[nt][1].x);
                }
            }
        }

#pragma unroll
        for (int mt = 0; mt < 2; mt++) {
#pragma unroll
            for (int hf = 0; hf < 2; hf++) {
                float mx = -1e30f;
#pragma unroll
                for (int nt = 0; nt < 8; nt++)
                    mx = fmaxf(mx, fmaxf(s[mt][nt][2 * hf], s[mt][nt][2 * hf + 1]));
                mx = fmaxf(mx, __shfl_xor_sync(0xffffffffu, mx, 1));
                mx = fmaxf(mx, __shfl_xor_sync(0xffffffffu, mx, 2));
                float m_new = fmaxf(m_i[mt][hf], mx);
                float alpha = __expf(m_i[mt][hf] - m_new);
                float rs = 0.0f;
#pragma unroll
                for (int nt = 0; nt < 8; nt++) {
                    s[mt][nt][2 * hf]     = __expf(s[mt][nt][2 * hf] - m_new);
                    s[mt][nt][2 * hf + 1] = __expf(s[mt][nt][2 * hf + 1] - m_new);
                    rs += s[mt][nt][2 * hf] + s[mt][nt][2 * hf + 1];
                }
                rs += __shfl_xor_sync(0xffffffffu, rs, 1);
                rs += __shfl_xor_sync(0xffffffffu, rs, 2);
                l_i[mt][hf] = l_i[mt][hf] * alpha + rs;
                m_i[mt][hf] = m_new;
#pragma unroll
                for (int nt = 0; nt < 8; nt++) {
                    acc[mt][nt][2 * hf]     *= alpha;
                    acc[mt][nt][2 * hf + 1] *= alpha;
                }
            }
        }

#pragma unroll
        for (int ks = 0; ks < 4; ks++) {
            uint32_t vh[8][2], vl[8][2];
#pragma unroll
            for (int nt = 0; nt < 8; nt++) {
                const int n  = nt * 8 + qr;
                const int k0 = ks * 16 + 2 * qc;
                float f0 = Vcur[k0 * VST + n];
                float f1 = Vcur[(k0 + 1) * VST + n];
                split2(f0, f1, vh[nt][0], vl[nt][0]);
                float f2 = Vcur[(k0 + 8) * VST + n];
                float f3 = Vcur[(k0 + 9) * VST + n];
                split2(f2, f3, vh[nt][1], vl[nt][1]);
            }
#pragma unroll
            for (int mt = 0; mt < 2; mt++) {
                uint32_t ph0, pl0, ph1, pl1, ph2, pl2, ph3, pl3;
                split2(s[mt][2 * ks][0],     s[mt][2 * ks][1],     ph0, pl0);
                split2(s[mt][2 * ks][2],     s[mt][2 * ks][3],     ph1, pl1);
                split2(s[mt][2 * ks + 1][0], s[mt][2 * ks + 1][1], ph2, pl2);
                split2(s[mt][2 * ks + 1][2], s[mt][2 * ks + 1][3], ph3, pl3);
#pragma unroll
                for (int nt = 0; nt < 8; nt++) {
                    mma_bf16(acc[mt][nt], ph0, ph1, ph2, ph3, vh[nt][0], vh[nt][1]);
                    mma_bf16(acc[mt][nt], ph0, ph1, ph2, ph3, vl[nt][0], vl[nt][1]);
                    mma_bf16(acc[mt][nt], pl0, pl1, pl2, pl3, vh[nt][0], vh[nt][1]);
                }
            }
        }
    }

#pragma unroll
    for (int mt = 0; mt < 2; mt++) {
        const float i0 = 1.0f / l_i[mt][0];
        const float i1 = 1.0f / l_i[mt][1];
        float* d0 = O + (size_t)(qt * 128 + wm + mt * 16 + qr) * DM + h * DH;
        float* d1 = d0 + (size_t)8 * DM;
#pragma unroll
        for (int nt = 0; nt < 8; nt++) {
            *(float2*)(d0 + nt * 8 + 2 * qc) =
                make_float2(acc[mt][nt][0] * i0, acc[mt][nt][1] * i0);
            *(float2*)(d1 + nt * 8 + 2 * qc) =
                make_float2(acc[mt][nt][2] * i1, acc[mt][nt][3] * i1);
        }
    }
}

// ==============================================================================
// launch (R13 structure; GEMMs swapped to 2-term fp16)
// ==============================================================================
extern "C" void kernel_launch(void* const* d_in, const int* in_sizes, int n_in,
                              void* d_out, int out_size)
{
    const float* x     = (const float*)d_in[0];
    const float* W_q   = (const float*)d_in[1];
    const float* b_q   = (const float*)d_in[2];
    const float* W_kv  = (const float*)d_in[3];
    const float* b_kv  = (const float*)d_in[4];
    const float* W_out = (const float*)d_in[5];
    const float* b_out = (const float*)d_in[6];
    float* out = (float*)d_out;

    float *qbuf, *kvbuf, *abuf;
    cudaGetSymbolAddress((void**)&qbuf, g_Q);
    cudaGetSymbolAddress((void**)&kvbuf, g_KV);
    cudaGetSymbolAddress((void**)&abuf, g_attn);

    cudaFuncSetAttribute(flash_attn_bf16, cudaFuncAttributeMaxDynamicSharedMemorySize, FA_SMEM);
    cudaFuncSetAttribute(tgemm_f16_nt_bias, cudaFuncAttributeMaxDynamicSharedMemorySize, TG_SMEM);

    freq_kernel<<<1, 32>>>();

    // Q projection: [2048,2048]
    tgemm_f16_nt_bias<<<dim3(DM / 128, S_LEN / 128), 128, TG_SMEM>>>(
        x, W_q, b_q, qbuf, S_LEN, DM, DM);

    // KV projection: [2048,1024]
    tgemm_f16_nt_bias<<<dim3(KV_W / 128, S_LEN / 128), 128, TG_SMEM>>>(
        x, W_kv, b_kv, kvbuf, S_LEN, KV_W, DM);

    // RoPE
    rope_kernel<<<(S_LEN * QH * 32 + 255) / 256, 256>>>(qbuf, QH, DM);
    rope_kernel<<<(S_LEN * KVH * 32 + 255) / 256, 256>>>(kvbuf, KVH, KV_W);

    // Flash attention (R13 exact, 3-term bf16)
    flash_attn_bf16<<<dim3(S_LEN / 128, QH), 128, FA_SMEM>>>(qbuf, kvbuf, abuf);

    // Output projection: [2048,2048]
    tgemm_f16_nt_bias<<<dim3(DM / 128, S_LEN / 128), 128, TG_SMEM>>>(
        abuf, W_out, b_out, out, S_LEN, DM, DM);
}

// round 17
// speedup vs baseline: 1.8367x; 1.1321x over previous
#include <cuda_runtime.h>
#include <cuda_fp16.h>
#include <math.h>
#include <stdint.h>

#define S_LEN 2048
#define DM    2048
#define QH    32
#define KVH   8
#define DH    64
#define KV_W  (2 * KVH * DH)   // 1024

// ---------------- scratch (allocation-free: __device__ globals) ----------------
__device__ float g_Q[S_LEN * DM];        // fp32 Q proj (rope'd in place)
__device__ float g_KV[S_LEN * KV_W];     // fp32 KV proj (K rope'd in place)
__device__ float g_attn[S_LEN * DM];     // fp32 attention output
__device__ float g_freq[32];             // rope frequency table

// ============================ helpers ====================================
__device__ __forceinline__ uint32_t smem_u32(const void* p) {
    uint32_t a;
    asm("{ .reg .u64 t; cvta.to.shared.u64 t, %1; cvt.u32.u64 %0, t; }" : "=r"(a) : "l"(p));
    return a;
}
#define CP_ASYNC16(dst, src) \
    asm volatile("cp.async.cg.shared.global [%0], [%1], 16;" :: "r"(dst), "l"(src))
#define CP_COMMIT() asm volatile("cp.async.commit_group;" ::: "memory")
#define CP_WAIT1()  asm volatile("cp.async.wait_group 1;" ::: "memory")
#define CP_WAIT0()  asm volatile("cp.async.wait_group 0;" ::: "memory")

// ---- fp16 helpers ----
__device__ __forceinline__ uint32_t pack_f16(float f0_lo, float f1_hi) {
    __half2 h = __floats2half2_rn(f0_lo, f1_hi);
    return *(uint32_t*)&h;
}
// 2-term split: f = h + l with fp16 rounding (l residual, exact to ~2^-23)
__device__ __forceinline__ void split2h(float f0, float f1, uint32_t& h, uint32_t& l) {
    __half2 hh = __floats2half2_rn(f0, f1);
    float2 hf = __half22float2(hh);
    __half2 ll = __floats2half2_rn(f0 - hf.x, f1 - hf.y);
    h = *(uint32_t*)&hh;
    l = *(uint32_t*)&ll;
}
__device__ __forceinline__ void mma_f16(float* d,
                                        uint32_t a0, uint32_t a1, uint32_t a2, uint32_t a3,
                                        uint32_t b0, uint32_t b1) {
    asm volatile(
        "mma.sync.aligned.m16n8k16.row.col.f32.f16.f16.f32 "
        "{%0,%1,%2,%3}, {%4,%5,%6,%7}, {%8,%9}, {%0,%1,%2,%3};"
        : "+f"(d[0]), "+f"(d[1]), "+f"(d[2]), "+f"(d[3])
        : "r"(a0), "r"(a1), "r"(a2), "r"(a3), "r"(b0), "r"(b1));
}

// ==============================================================================
// 2-term FP16 GEMM (R16 EXACT — proven 987us component)
// C = A @ B^T + bias. A = Ah + Al (split); B = Bh (fp16 rn). 2 MMAs per k16.
// 128x128 CTA tile, BK=16, 128 threads (4 warps, 64x64 warp tiles).
// ==============================================================================
#define BK     16
#define SSTR   24
#define ST_F   (128 * SSTR)
#define STG_F  (2 * ST_F)
#define NSTG   3
#define TG_SMEM (NSTG * STG_F * 4)  // 73728 B

__global__ __launch_bounds__(128, 2)
void tgemm_f16_nt_bias(const float* __restrict__ A, const float* __restrict__ B,
                       const float* __restrict__ bias, float* __restrict__ C,
                       int M, int N, int K)
{
    extern __shared__ float sm[];
    const uint32_t smb = smem_u32(sm);

    const int tid  = threadIdx.x;
    const int wid  = tid >> 5;
    const int lane = tid & 31;
    const int qr   = lane >> 2;
    const int qc   = lane & 3;
    const int wm   = (wid & 1) * 64;
    const int wn   = (wid >> 1) * 64;
    const int brow = blockIdx.y * 128;
    const int bcol = blockIdx.x * 128;

    const float* Ag = A + (size_t)(brow + tid) * K;
    const float* Bg = B + (size_t)(bcol + tid) * K;
    const uint32_t dst_off = (uint32_t)(tid * SSTR) * 4;

    const int NT = K / BK;

    auto issue_stage = [&](int kt) {
        const uint32_t da = smb + (uint32_t)((kt % NSTG) * STG_F) * 4 + dst_off;
        const uint32_t db = da + ST_F * 4;
        const float* sa = Ag + kt * BK;
        const float* sb = Bg + kt * BK;
#pragma unroll
        for (int j = 0; j < 4; j++) {
            CP_ASYNC16(da + 16 * j, sa + 4 * j);
            CP_ASYNC16(db + 16 * j, sb + 4 * j);
        }
    };

    float acc[4][8][4];
#pragma unroll
    for (int mt = 0; mt < 4; mt++)
#pragma unroll
        for (int nt = 0; nt < 8; nt++)
#pragma unroll
            for (int i = 0; i < 4; i++) acc[mt][nt][i] = 0.0f;

    issue_stage(0); CP_COMMIT();
    issue_stage(1); CP_COMMIT();

    for (int kt = 0; kt < NT; kt++) {
        CP_WAIT1();
        __syncthreads();

        if (kt + 2 < NT) issue_stage(kt + 2);
        CP_COMMIT();

        const float* As = sm + (kt % NSTG) * STG_F;
        const float* Bs = As + ST_F;

        uint32_t bh[8][2];
#pragma unroll
        for (int nt = 0; nt < 8; nt++) {
            const int off = (wn + nt * 8 + qr) * SSTR + 2 * qc;
            float2 f = *(const float2*)&Bs[off];
            float2 g = *(const float2*)&Bs[off + 8];
            bh[nt][0] = pack_f16(f.x, f.y);
            bh[nt][1] = pack_f16(g.x, g.y);
        }
#pragma unroll
        for (int mt = 0; mt < 4; mt++) {
            const int off = (wm + mt * 16 + qr) * SSTR + 2 * qc;
            float2 f0 = *(const float2*)&As[off];
            float2 f1 = *(const float2*)&As[off + 8 * SSTR];
            float2 f2 = *(const float2*)&As[off + 8];
            float2 f3 = *(const float2*)&As[off + 8 * SSTR + 8];
            uint32_t ah0, ah1, ah2, ah3, al0, al1, al2, al3;
            split2h(f0.x, f0.y, ah0, al0);
            split2h(f1.x, f1.y, ah1, al1);
            split2h(f2.x, f2.y, ah2, al2);
            split2h(f3.x, f3.y, ah3, al3);
#pragma unroll
            for (int nt = 0; nt < 8; nt++) {
                mma_f16(acc[mt][nt], ah0, ah1, ah2, ah3, bh[nt][0], bh[nt][1]);
                mma_f16(acc[mt][nt], al0, al1, al2, al3, bh[nt][0], bh[nt][1]);
            }
        }
        __syncthreads();
    }

#pragma unroll
    for (int mt = 0; mt < 4; mt++) {
        const int row = brow + wm + mt * 16 + qr;
#pragma unroll
        for (int nt = 0; nt < 8; nt++) {
            const int col = bcol + wn + nt * 8 + qc * 2;
            const float b0 = bias[col], b1 = bias[col + 1];
            *(float2*)(C + (size_t)row * N + col) =
                make_float2(acc[mt][nt][0] + b0, acc[mt][nt][1] + b1);
            *(float2*)(C + (size_t)(row + 8) * N + col) =
                make_float2(acc[mt][nt][2] + b0, acc[mt][nt][3] + b1);
        }
    }
}

// ==============================================================================
// RoPE (R13 exact)
// ==============================================================================
__global__ void freq_kernel()
{
    int j = threadIdx.x;
    if (j < 32) g_freq[j] = (float)pow(10000.0, -(double)j / 32.0);
}

__global__ void rope_kernel(float* __restrict__ X, int H, int rowstride)
{
    int idx = blockIdx.x * blockDim.x + threadIdx.x;
    int total = S_LEN * H * (DH / 2);
    if (idx >= total) return;

    int j = idx & 31;
    int t = idx >> 5;
    int h = t % H;
    int s = t / H;

    float theta = (float)s * g_freq[j];
    float sn, cs;
    sincosf(theta, &sn, &cs);

    float* p = X + (size_t)s * rowstride + h * DH + 2 * j;
    float2 v = *(float2*)p;
    float2 o;
    o.x = v.x * cs - v.y * sn;
    o.y = v.x * sn + v.y * cs;
    *(float2*)p = o;
}

// ==============================================================================
// Flash attention, 2-term fp16 (R13 pipeline):
//  S = (Qh+Ql) @ Kh^T  (2 MMAs/k16; K single fp16)
//  O += (Ph+Pl) @ Vh   (2 MMAs/k16; V single fp16, converted in-loop)
//  V: cp.async fp32 double buffer; K: register prefetch + pack-only fill;
//  P: fragments in registers. 128 q-rows x head, 4 warps.
// smem: QHL(uint2) 36864 + Kh(uint32) 9216 + V 2x17408 = 80896 B -> occ 2.
// ==============================================================================
#define QST 36        // uint2 stride for QHL rows
#define KST 36        // uint32 stride for Kh rows
#define VST 68        // float stride for V rows
#define VBUF_F (64 * VST)                     // 4352 floats per V buffer
#define OFF_KH  36864                         // after QHL (128*36*8)
#define OFF_VS  (OFF_KH + 64 * KST * 4)       // 36864 + 9216 = 46080
#define FA_SMEM (OFF_VS + 2 * VBUF_F * 4)     // 46080 + 34816 = 80896

__global__ __launch_bounds__(128, 2)
void flash_attn_f16(const float* __restrict__ Q, const float* __restrict__ KV,
                    float* __restrict__ O)
{
    extern __shared__ char smc[];
    const uint32_t smb = smem_u32(smc);
    uint2*    QHL = (uint2*)smc;
    uint32_t* Kh  = (uint32_t*)(smc + OFF_KH);
    float*    Vs  = (float*)(smc + OFF_VS);

    const int qt   = blockIdx.x;
    const int h    = blockIdx.y;
    const int hk   = h >> 2;
    const int tid  = threadIdx.x;
    const int wid  = tid >> 5;
    const int lane = tid & 31;
    const int qr   = lane >> 2;
    const int qc   = lane & 3;
    const int wm   = wid * 32;

    // loader mapping for K/V tiles: thread owns key-row (tid>>1), 32-dim half
    const int lrow  = tid >> 1;
    const int lhalf = (tid & 1) * 32;
    const float* kbase = KV + (size_t)lrow * KV_W + hk * DH + lhalf;
    const float* vbase = kbase + KVH * DH;
    uint32_t* kdst = Kh + lrow * KST + (lhalf >> 1);
    const uint32_t vdst_off = smb + OFF_VS + (uint32_t)(lrow * VST + lhalf) * 4;

    auto issue_V = [&](int kt) {
        const float* src = vbase + (size_t)(kt * 64) * KV_W;
        uint32_t dst = vdst_off + (uint32_t)((kt & 1) * VBUF_F) * 4;
#pragma unroll
        for (int j = 0; j < 8; j++) CP_ASYNC16(dst + 16 * j, src + 4 * j);
    };

    // ---- Q fill: scale by 1/8, fp16 hi/lo split, pack ----
    {
        const float* src = Q + (size_t)(qt * 128 + tid) * DM + h * DH;
        uint2* dst = QHL + tid * QST;
#pragma unroll
        for (int j = 0; j < 16; j++) {
            float4 v = *(const float4*)(src + 4 * j);
            uint32_t h01, l01, h23, l23;
            split2h(v.x * 0.125f, v.y * 0.125f, h01, l01);
            split2h(v.z * 0.125f, v.w * 0.125f, h23, l23);
            *(uint4*)(dst + 2 * j) = make_uint4(h01, l01, h23, l23);
        }
    }

    // ---- prologue: V(0) in flight, K(0) in registers ----
    issue_V(0); CP_COMMIT();
    float4 kreg[8];
    {
        const float* src = kbase;
#pragma unroll
        for (int j = 0; j < 8; j++) kreg[j] = *(const float4*)(src + 4 * j);
    }

    float m_i[2][2], l_i[2][2];
#pragma unroll
    for (int mt = 0; mt < 2; mt++)
#pragma unroll
        for (int hf = 0; hf < 2; hf++) { m_i[mt][hf] = -1e30f; l_i[mt][hf] = 0.0f; }

    float acc[2][8][4];
#pragma unroll
    for (int mt = 0; mt < 2; mt++)
#pragma unroll
        for (int nt = 0; nt < 8; nt++)
#pragma unroll
            for (int i = 0; i < 4; i++) acc[mt][nt][i] = 0.0f;

    for (int kt = 0; kt < 32; kt++) {
        __syncthreads();   // all warps done reading Kh(kt-1) and V buf (kt+1)&1

        // ---- K fill from prefetched registers: pack-only (fp16 hi) + STS ----
#pragma unroll
        for (int j = 0; j < 4; j++) {
            uint32_t u0 = pack_f16(kreg[2 * j].x,     kreg[2 * j].y);
            uint32_t u1 = pack_f16(kreg[2 * j].z,     kreg[2 * j].w);
            uint32_t u2 = pack_f16(kreg[2 * j + 1].x, kreg[2 * j + 1].y);
            uint32_t u3 = pack_f16(kreg[2 * j + 1].z, kreg[2 * j + 1].w);
            *(uint4*)(kdst + 4 * j) = make_uint4(u0, u1, u2, u3);
        }
        // prefetch K(kt+1) into registers (latency covered by compute below)
        if (kt + 1 < 32) {
            const float* src = kbase + (size_t)((kt + 1) * 64) * KV_W;
#pragma unroll
            for (int j = 0; j < 8; j++) kreg[j] = *(const float4*)(src + 4 * j);
        }
        // V pipeline: issue kt+1, wait for kt
        if (kt + 1 < 32) { issue_V(kt + 1); CP_COMMIT(); CP_WAIT1(); }
        else             { CP_WAIT0(); }
        __syncthreads();

        const float* Vcur = Vs + (kt & 1) * VBUF_F;

        // ---- S = (Qh+Ql) @ Kh^T (2 MMAs per k16) ----
        float s[2][8][4];
#pragma unroll
        for (int mt = 0; mt < 2; mt++)
#pragma unroll
            for (int nt = 0; nt < 8; nt++)
#pragma unroll
                for (int i = 0; i < 4; i++) s[mt][nt][i] = 0.0f;

#pragma unroll
        for (int ks = 0; ks < 4; ks++) {
            uint32_t bk[8][2];
#pragma unroll
            for (int nt = 0; nt < 8; nt++) {
                const int kb = (nt * 8 + qr) * KST + ks * 8 + qc;
                bk[nt][0] = Kh[kb];
                bk[nt][1] = Kh[kb + 4];
            }
#pragma unroll
            for (int mt = 0; mt < 2; mt++) {
                const int qb = (wm + mt * 16 + qr) * QST + ks * 8 + qc;
                uint2 a0 = QHL[qb];
                uint2 a1 = QHL[qb + 8 * QST];
                uint2 a2 = QHL[qb + 4];
                uint2 a3 = QHL[qb + 8 * QST + 4];
#pragma unroll
                for (int nt = 0; nt < 8; nt++) {
                    mma_f16(s[mt][nt], a0.x, a1.x, a2.x, a3.x, bk[nt][0], bk[nt][1]);
                    mma_f16(s[mt][nt], a0.y, a1.y, a2.y, a3.y, bk[nt][0], bk[nt][1]);
                }
            }
        }

        // ---- online softmax (R13 exact) ----
#pragma unroll
        for (int mt = 0; mt < 2; mt++) {
#pragma unroll
            for (int hf = 0; hf < 2; hf++) {
                float mx = -1e30f;
#pragma unroll
                for (int nt = 0; nt < 8; nt++)
                    mx = fmaxf(mx, fmaxf(s[mt][nt][2 * hf], s[mt][nt][2 * hf + 1]));
                mx = fmaxf(mx, __shfl_xor_sync(0xffffffffu, mx, 1));
                mx = fmaxf(mx, __shfl_xor_sync(0xffffffffu, mx, 2));
                float m_new = fmaxf(m_i[mt][hf], mx);
                float alpha = __expf(m_i[mt][hf] - m_new);
                float rs = 0.0f;
#pragma unroll
                for (int nt = 0; nt < 8; nt++) {
                    s[mt][nt][2 * hf]     = __expf(s[mt][nt][2 * hf] - m_new);
                    s[mt][nt][2 * hf + 1] = __expf(s[mt][nt][2 * hf + 1] - m_new);
                    rs += s[mt][nt][2 * hf] + s[mt][nt][2 * hf + 1];
                }
                rs += __shfl_xor_sync(0xffffffffu, rs, 1);
                rs += __shfl_xor_sync(0xffffffffu, rs, 2);
                l_i[mt][hf] = l_i[mt][hf] * alpha + rs;
                m_i[mt][hf] = m_new;
#pragma unroll
                for (int nt = 0; nt < 8; nt++) {
                    acc[mt][nt][2 * hf]     *= alpha;
                    acc[mt][nt][2 * hf + 1] *= alpha;
                }
            }
        }

        // ---- acc += (Ph+Pl) @ Vh: P frags in registers, V packed in-loop ----
#pragma unroll
        for (int ks = 0; ks < 4; ks++) {
            uint32_t vh[8][2];
#pragma unroll
            for (int nt = 0; nt < 8; nt++) {
                const int n  = nt * 8 + qr;
                const int k0 = ks * 16 + 2 * qc;
                vh[nt][0] = pack_f16(Vcur[k0 * VST + n],       Vcur[(k0 + 1) * VST + n]);
                vh[nt][1] = pack_f16(Vcur[(k0 + 8) * VST + n], Vcur[(k0 + 9) * VST + n]);
            }
#pragma unroll
            for (int mt = 0; mt < 2; mt++) {
                uint32_t ph0, pl0, ph1, pl1, ph2, pl2, ph3, pl3;
                split2h(s[mt][2 * ks][0],     s[mt][2 * ks][1],     ph0, pl0);
                split2h(s[mt][2 * ks][2],     s[mt][2 * ks][3],     ph1, pl1);
                split2h(s[mt][2 * ks + 1][0], s[mt][2 * ks + 1][1], ph2, pl2);
                split2h(s[mt][2 * ks + 1][2], s[mt][2 * ks + 1][3], ph3, pl3);
#pragma unroll
                for (int nt = 0; nt < 8; nt++) {
                    mma_f16(acc[mt][nt], ph0, ph1, ph2, ph3, vh[nt][0], vh[nt][1]);
                    mma_f16(acc[mt][nt], pl0, pl1, pl2, pl3, vh[nt][0], vh[nt][1]);
                }
            }
        }
    }

    // ---- epilogue: normalize, store fp32 ----
#pragma unroll
    for (int mt = 0; mt < 2; mt++) {
        const float i0 = 1.0f / l_i[mt][0];
        const float i1 = 1.0f / l_i[mt][1];
        float* d0 = O + (size_t)(qt * 128 + wm + mt * 16 + qr) * DM + h * DH;
        float* d1 = d0 + (size_t)8 * DM;
#pragma unroll
        for (int nt = 0; nt < 8; nt++) {
            *(float2*)(d0 + nt * 8 + 2 * qc) =
                make_float2(acc[mt][nt][0] * i0, acc[mt][nt][1] * i0);
            *(float2*)(d1 + nt * 8 + 2 * qc) =
                make_float2(acc[mt][nt][2] * i1, acc[mt][nt][3] * i1);
        }
    }
}

// ==============================================================================
// launch (R16 structure; attention swapped to 2-term fp16)
// ==============================================================================
extern "C" void kernel_launch(void* const* d_in, const int* in_sizes, int n_in,
                              void* d_out, int out_size)
{
    const float* x     = (const float*)d_in[0];
    const float* W_q   = (const float*)d_in[1];
    const float* b_q   = (const float*)d_in[2];
    const float* W_kv  = (const float*)d_in[3];
    const float* b_kv  = (const float*)d_in[4];
    const float* W_out = (const float*)d_in[5];
    const float* b_out = (const float*)d_in[6];
    float* out = (float*)d_out;

    float *qbuf, *kvbuf, *abuf;
    cudaGetSymbolAddress((void**)&qbuf, g_Q);
    cudaGetSymbolAddress((void**)&kvbuf, g_KV);
    cudaGetSymbolAddress((void**)&abuf, g_attn);

    cudaFuncSetAttribute(flash_attn_f16, cudaFuncAttributeMaxDynamicSharedMemorySize, FA_SMEM);
    cudaFuncSetAttribute(tgemm_f16_nt_bias, cudaFuncAttributeMaxDynamicSharedMemorySize, TG_SMEM);

    freq_kernel<<<1, 32>>>();

    // Q projection: [2048,2048]
    tgemm_f16_nt_bias<<<dim3(DM / 128, S_LEN / 128), 128, TG_SMEM>>>(
        x, W_q, b_q, qbuf, S_LEN, DM, DM);

    // KV projection: [2048,1024]
    tgemm_f16_nt_bias<<<dim3(KV_W / 128, S_LEN / 128), 128, TG_SMEM>>>(
        x, W_kv, b_kv, kvbuf, S_LEN, KV_W, DM);

    // RoPE
    rope_kernel<<<(S_LEN * QH * 32 + 255) / 256, 256>>>(qbuf, QH, DM);
    rope_kernel<<<(S_LEN * KVH * 32 + 255) / 256, 256>>>(kvbuf, KVH, KV_W);

    // Flash attention (2-term fp16)
    flash_attn_f16<<<dim3(S_LEN / 128, QH), 128, FA_SMEM>>>(qbuf, kvbuf, abuf);

    // Output projection: [2048,2048]
    tgemm_f16_nt_bias<<<dim3(DM / 128, S_LEN / 128), 128, TG_SMEM>>>(
        abuf, W_out, b_out, out, S_LEN, DM, DM);
}